// round 14
// baseline (speedup 1.0000x reference)
#include <cuda_runtime.h>
#include <cuda_fp16.h>

// 5-level db4 DWT, symmetric extension. fp16 smem cascade (fp32 scalar FMA),
// 4 outputs/thread from 2 conflict-free aligned LDS.128. R5 body, NT=192:
// 6 warps/CTA admits 10 CTAs/SM (60 warps, 94% occ) AND cuts pass-
// quantization waste (2688 vs 3072 slots/row). Streaming cache hints on the
// read-once/write-once gmem streams.

#define NROWS 4096
#define NT    192

#define L0 4096
#define L1 2051
#define L2 1029
#define L3 518
#define L4 262
#define L5 134

#define O_APPROX 0
#define O_D5 (NROWS * L5)
#define O_D4 (O_D5 + NROWS * L5)
#define O_D3 (O_D4 + NROWS * L4)
#define O_D2 (O_D3 + NROWS * L3)
#define O_D1 (O_D2 + NROWS * L2)

// Reversed filters: y[j] = sum_r RF[r] * ext[2j + r]
#define RLO0  0.23037781330885523f
#define RLO1  0.7148465705525415f
#define RLO2  0.6308807679295904f
#define RLO3 -0.02798376941698385f
#define RLO4 -0.18703481171888114f
#define RLO5  0.030841381835986965f
#define RLO6  0.032883011666982945f
#define RLO7 -0.010597401784997278f

#define RHI0 -0.010597401784997278f
#define RHI1 -0.032883011666982945f
#define RHI2  0.030841381835986965f
#define RHI3  0.18703481171888114f
#define RHI4 -0.02798376941698385f
#define RHI5 -0.6308807679295904f
#define RHI6  0.7148465705525415f
#define RHI7 -0.23037781330885523f

__device__ __forceinline__ int coff(int s) { return ((2 * s + 4) & 7) + 6; }

// One level. q: fp16 buffer, ext[i] = q[c+i], input length N, M=(N+7)/2 outputs.
// cD -> fp32 gmem (STG.128 via sigma shift, streaming). Non-LAST: cA -> fp16
// buffer qn (ext base cn) incl. mirror pads. LAST: cA -> fp32 gmem cAg.
template<bool LAST>
__device__ __forceinline__ void dwt16(const __half* __restrict__ q, int c,
                                      int N, int sigma,
                                      __half* __restrict__ qn, int cn,
                                      float* __restrict__ cD,
                                      float* __restrict__ cAg, int tid)
{
    const int M  = (N + 7) >> 1;
    const int NB = (M + sigma + 3) >> 2;
    for (int T = tid; T < NB; T += NT) {
        const int j0 = 4 * T - sigma;
        const int h0 = c + 8 * T - 2 * sigma - 2;   // ≡ 0 (mod 8) by choice of c
        const uint4 u0 = *reinterpret_cast<const uint4*>(q + h0);
        const uint4 u1 = *reinterpret_cast<const uint4*>(q + h0 + 8);

        float w[14];
        {
            const __half2* ha = reinterpret_cast<const __half2*>(&u0);
            const __half2* hb = reinterpret_cast<const __half2*>(&u1);
            float2 t;
            t = __half22float2(ha[1]); w[0]  = t.x; w[1]  = t.y;
            t = __half22float2(ha[2]); w[2]  = t.x; w[3]  = t.y;
            t = __half22float2(ha[3]); w[4]  = t.x; w[5]  = t.y;
            t = __half22float2(hb[0]); w[6]  = t.x; w[7]  = t.y;
            t = __half22float2(hb[1]); w[8]  = t.x; w[9]  = t.y;
            t = __half22float2(hb[2]); w[10] = t.x; w[11] = t.y;
            t = __half22float2(hb[3]); w[12] = t.x; w[13] = t.y;
        }

        float lo[4], hi[4];
#pragma unroll
        for (int m = 0; m < 4; m++) {
            float l = RLO0 * w[2 * m];
            l = fmaf(RLO1, w[2 * m + 1], l);
            l = fmaf(RLO2, w[2 * m + 2], l);
            l = fmaf(RLO3, w[2 * m + 3], l);
            l = fmaf(RLO4, w[2 * m + 4], l);
            l = fmaf(RLO5, w[2 * m + 5], l);
            l = fmaf(RLO6, w[2 * m + 6], l);
            l = fmaf(RLO7, w[2 * m + 7], l);
            lo[m] = l;
            float h = RHI0 * w[2 * m];
            h = fmaf(RHI1, w[2 * m + 1], h);
            h = fmaf(RHI2, w[2 * m + 2], h);
            h = fmaf(RHI3, w[2 * m + 3], h);
            h = fmaf(RHI4, w[2 * m + 4], h);
            h = fmaf(RHI5, w[2 * m + 5], h);
            h = fmaf(RHI6, w[2 * m + 6], h);
            h = fmaf(RHI7, w[2 * m + 7], h);
            hi[m] = h;
        }

        const bool interior = (j0 >= 0) && (j0 + 4 <= M);
        if (interior) {
            __stcs(reinterpret_cast<float4*>(cD + j0),
                   make_float4(hi[0], hi[1], hi[2], hi[3]));
            if (LAST)
                __stcs(reinterpret_cast<float4*>(cAg + j0),
                       make_float4(lo[0], lo[1], lo[2], lo[3]));
        } else {
#pragma unroll
            for (int m = 0; m < 4; m++) {
                const int j = j0 + m;
                if (j >= 0 && j < M) {
                    cD[j] = hi[m];
                    if (LAST) cAg[j] = lo[m];
                }
            }
        }

        if (!LAST) {
            if (interior && j0 > 5 && j0 + 3 < M - 8) {
#pragma unroll
                for (int m = 0; m < 4; m++)
                    qn[cn + 6 + j0 + m] = __float2half_rn(lo[m]);
            } else {
#pragma unroll
                for (int m = 0; m < 4; m++) {
                    const int j = j0 + m;
                    if (j < 0 || j >= M) continue;
                    const __half v = __float2half_rn(lo[m]);
                    qn[cn + 6 + j] = v;                      // interior
                    if (j <= 5)      qn[cn + 5 - j] = v;     // left mirror
                    if (j >= M - 8)  qn[cn + 2 * M + 5 - j] = v; // right mirror
                }
            }
        }
    }
}

__global__ __launch_bounds__(NT)
void wavelet5_kernel(const float* __restrict__ x, float* __restrict__ out) {
    __shared__ __align__(16) __half IN16[4160];  // lvl1 input / lvl3 output / lvl4 input
    __shared__ __align__(16) __half A16[2112];   // lvl1 out / lvl2 in / lvl4 out / lvl5 in
    __shared__ __align__(16) __half B16[1088];   // lvl2 out / lvl3 in

    const int row = blockIdx.x;
    const int tid = threadIdx.x;

    // Per-level gmem alignment shifts (floats mod 4 of each cD row base)
    const int s1 = (3 * row) & 3;   // L1=2051 ≡ 3 (mod 4)
    const int s2 = row & 3;         // L2=1029 ≡ 1
    const int s3 = (2 * row) & 3;   // L3,L4,L5 ≡ 2
    const int c1 = coff(s1), c2 = coff(s2), c3 = coff(s3);

    const float* __restrict__ xr = x + (size_t)row * L0;

    // Build fp16 extended input: ext[i] = IN16[c1+i]
    {
        const float4* __restrict__ x4 = reinterpret_cast<const float4*>(xr);
        __half2* __restrict__ dst = reinterpret_cast<__half2*>(IN16 + c1 + 6);
#pragma unroll 2
        for (int u = tid; u < L0 / 4; u += NT) {
            const float4 v = __ldcs(x4 + u);
            dst[2 * u]     = __floats2half2_rn(v.x, v.y);
            dst[2 * u + 1] = __floats2half2_rn(v.z, v.w);
        }
        if (tid < 6) {
            IN16[c1 + tid] = __float2half_rn(xr[5 - tid]);            // left ext
        } else if (tid < 14) {
            const int t = tid - 6;
            IN16[c1 + L0 + 6 + t] = __float2half_rn(xr[L0 - 1 - t]);  // right ext
        }
    }
    __syncthreads();

    float* __restrict__ d1 = out + O_D1 + (size_t)row * L1;
    float* __restrict__ d2 = out + O_D2 + (size_t)row * L2;
    float* __restrict__ d3 = out + O_D3 + (size_t)row * L3;
    float* __restrict__ d4 = out + O_D4 + (size_t)row * L4;
    float* __restrict__ d5 = out + O_D5 + (size_t)row * L5;
    float* __restrict__ ap = out + O_APPROX + (size_t)row * L5;

    dwt16<false>(IN16, c1, L0, s1, A16, c2, d1, nullptr, tid);  // 4096 -> 2051
    __syncthreads();
    dwt16<false>(A16, c2, L1, s2, B16, c3, d2, nullptr, tid);   // 2051 -> 1029
    __syncthreads();
    dwt16<false>(B16, c3, L2, s3, IN16, c3, d3, nullptr, tid);  // 1029 -> 518
    __syncthreads();
    dwt16<false>(IN16, c3, L3, s3, A16, c3, d4, nullptr, tid);  // 518  -> 262
    __syncthreads();
    dwt16<true>(A16, c3, L4, s3, nullptr, 0, d5, ap, tid);      // 262  -> 134
}

extern "C" void kernel_launch(void* const* d_in, const int* in_sizes, int n_in,
                              void* d_out, int out_size) {
    const float* x = (const float*)d_in[0];
    float* out = (float*)d_out;
    (void)in_sizes; (void)n_in; (void)out_size;
    wavelet5_kernel<<<NROWS, NT>>>(x, out);
}

// round 15
// speedup vs baseline: 1.0625x; 1.0625x over previous
#include <cuda_runtime.h>
#include <cuda_fp16.h>

// 5-level db4 DWT, symmetric extension. fp16 smem cascade (fp32 math, fp32
// gmem outputs). Per level: 4 outputs/thread, window = 14 halfs loaded as
// 2 conflict-free aligned LDS.128 (16B lane stride). Per-row shift sigma
// aligns cD to STG.128; smem offset c = ((2*sigma+4)&7)+6 keeps loads aligned.
// [R5 champion configuration — measured best across 14 rounds of variants.]

#define NROWS 4096
#define NT    256

#define L0 4096
#define L1 2051
#define L2 1029
#define L3 518
#define L4 262
#define L5 134

#define O_APPROX 0
#define O_D5 (NROWS * L5)
#define O_D4 (O_D5 + NROWS * L5)
#define O_D3 (O_D4 + NROWS * L4)
#define O_D2 (O_D3 + NROWS * L3)
#define O_D1 (O_D2 + NROWS * L2)

// Reversed filters: y[j] = sum_r RF[r] * ext[2j + r]
#define RLO0  0.23037781330885523f
#define RLO1  0.7148465705525415f
#define RLO2  0.6308807679295904f
#define RLO3 -0.02798376941698385f
#define RLO4 -0.18703481171888114f
#define RLO5  0.030841381835986965f
#define RLO6  0.032883011666982945f
#define RLO7 -0.010597401784997278f

#define RHI0 -0.010597401784997278f
#define RHI1 -0.032883011666982945f
#define RHI2  0.030841381835986965f
#define RHI3  0.18703481171888114f
#define RHI4 -0.02798376941698385f
#define RHI5 -0.6308807679295904f
#define RHI6  0.7148465705525415f
#define RHI7 -0.23037781330885523f

__device__ __forceinline__ int coff(int s) { return ((2 * s + 4) & 7) + 6; }

// One level. q: fp16 buffer, ext[i] = q[c+i], input length N, M=(N+7)/2 outputs.
// cD -> fp32 gmem (STG.128 via sigma shift). Non-LAST: cA -> fp16 buffer qn
// (ext base cn) incl. mirror pads. LAST: cA -> fp32 gmem cAg (same sigma).
template<bool LAST>
__device__ __forceinline__ void dwt16(const __half* __restrict__ q, int c,
                                      int N, int sigma,
                                      __half* __restrict__ qn, int cn,
                                      float* __restrict__ cD,
                                      float* __restrict__ cAg, int tid)
{
    const int M  = (N + 7) >> 1;
    const int NB = (M + sigma + 3) >> 2;
    for (int T = tid; T < NB; T += NT) {
        const int j0 = 4 * T - sigma;
        const int h0 = c + 8 * T - 2 * sigma - 2;   // ≡ 0 (mod 8) by choice of c
        const uint4 u0 = *reinterpret_cast<const uint4*>(q + h0);
        const uint4 u1 = *reinterpret_cast<const uint4*>(q + h0 + 8);

        float w[14];
        {
            const __half2* ha = reinterpret_cast<const __half2*>(&u0);
            const __half2* hb = reinterpret_cast<const __half2*>(&u1);
            float2 t;
            t = __half22float2(ha[1]); w[0]  = t.x; w[1]  = t.y;
            t = __half22float2(ha[2]); w[2]  = t.x; w[3]  = t.y;
            t = __half22float2(ha[3]); w[4]  = t.x; w[5]  = t.y;
            t = __half22float2(hb[0]); w[6]  = t.x; w[7]  = t.y;
            t = __half22float2(hb[1]); w[8]  = t.x; w[9]  = t.y;
            t = __half22float2(hb[2]); w[10] = t.x; w[11] = t.y;
            t = __half22float2(hb[3]); w[12] = t.x; w[13] = t.y;
        }

        float lo[4], hi[4];
#pragma unroll
        for (int m = 0; m < 4; m++) {
            float l = RLO0 * w[2 * m];
            l = fmaf(RLO1, w[2 * m + 1], l);
            l = fmaf(RLO2, w[2 * m + 2], l);
            l = fmaf(RLO3, w[2 * m + 3], l);
            l = fmaf(RLO4, w[2 * m + 4], l);
            l = fmaf(RLO5, w[2 * m + 5], l);
            l = fmaf(RLO6, w[2 * m + 6], l);
            l = fmaf(RLO7, w[2 * m + 7], l);
            lo[m] = l;
            float h = RHI0 * w[2 * m];
            h = fmaf(RHI1, w[2 * m + 1], h);
            h = fmaf(RHI2, w[2 * m + 2], h);
            h = fmaf(RHI3, w[2 * m + 3], h);
            h = fmaf(RHI4, w[2 * m + 4], h);
            h = fmaf(RHI5, w[2 * m + 5], h);
            h = fmaf(RHI6, w[2 * m + 6], h);
            h = fmaf(RHI7, w[2 * m + 7], h);
            hi[m] = h;
        }

        const bool interior = (j0 >= 0) && (j0 + 4 <= M);
        if (interior) {
            *reinterpret_cast<float4*>(cD + j0) =
                make_float4(hi[0], hi[1], hi[2], hi[3]);
            if (LAST)
                *reinterpret_cast<float4*>(cAg + j0) =
                    make_float4(lo[0], lo[1], lo[2], lo[3]);
        } else {
#pragma unroll
            for (int m = 0; m < 4; m++) {
                const int j = j0 + m;
                if (j >= 0 && j < M) {
                    cD[j] = hi[m];
                    if (LAST) cAg[j] = lo[m];
                }
            }
        }

        if (!LAST) {
            if (interior && j0 > 5 && j0 + 3 < M - 8) {
#pragma unroll
                for (int m = 0; m < 4; m++)
                    qn[cn + 6 + j0 + m] = __float2half_rn(lo[m]);
            } else {
#pragma unroll
                for (int m = 0; m < 4; m++) {
                    const int j = j0 + m;
                    if (j < 0 || j >= M) continue;
                    const __half v = __float2half_rn(lo[m]);
                    qn[cn + 6 + j] = v;                      // interior
                    if (j <= 5)      qn[cn + 5 - j] = v;     // left mirror
                    if (j >= M - 8)  qn[cn + 2 * M + 5 - j] = v; // right mirror
                }
            }
        }
    }
}

__global__ __launch_bounds__(NT)
void wavelet5_kernel(const float* __restrict__ x, float* __restrict__ out) {
    __shared__ __align__(16) __half IN16[4160];  // lvl1 input / lvl3 output / lvl4 input
    __shared__ __align__(16) __half A16[2112];   // lvl1 out / lvl2 in / lvl4 out / lvl5 in
    __shared__ __align__(16) __half B16[1088];   // lvl2 out / lvl3 in

    const int row = blockIdx.x;
    const int tid = threadIdx.x;

    // Per-level gmem alignment shifts (floats mod 4 of each cD row base)
    const int s1 = (3 * row) & 3;   // L1=2051 ≡ 3 (mod 4)
    const int s2 = row & 3;         // L2=1029 ≡ 1
    const int s3 = (2 * row) & 3;   // L3,L4,L5 ≡ 2
    const int c1 = coff(s1), c2 = coff(s2), c3 = coff(s3);

    const float* __restrict__ xr = x + (size_t)row * L0;

    // Build fp16 extended input: ext[i] = IN16[c1+i]
    {
        const float4* __restrict__ x4 = reinterpret_cast<const float4*>(xr);
        __half2* __restrict__ dst = reinterpret_cast<__half2*>(IN16 + c1 + 6);
#pragma unroll 4
        for (int u = tid; u < L0 / 4; u += NT) {
            const float4 v = x4[u];
            dst[2 * u]     = __floats2half2_rn(v.x, v.y);
            dst[2 * u + 1] = __floats2half2_rn(v.z, v.w);
        }
        if (tid < 6) {
            IN16[c1 + tid] = __float2half_rn(xr[5 - tid]);            // left ext
        } else if (tid < 14) {
            const int t = tid - 6;
            IN16[c1 + L0 + 6 + t] = __float2half_rn(xr[L0 - 1 - t]);  // right ext
        }
    }
    __syncthreads();

    float* __restrict__ d1 = out + O_D1 + (size_t)row * L1;
    float* __restrict__ d2 = out + O_D2 + (size_t)row * L2;
    float* __restrict__ d3 = out + O_D3 + (size_t)row * L3;
    float* __restrict__ d4 = out + O_D4 + (size_t)row * L4;
    float* __restrict__ d5 = out + O_D5 + (size_t)row * L5;
    float* __restrict__ ap = out + O_APPROX + (size_t)row * L5;

    dwt16<false>(IN16, c1, L0, s1, A16, c2, d1, nullptr, tid);  // 4096 -> 2051
    __syncthreads();
    dwt16<false>(A16, c2, L1, s2, B16, c3, d2, nullptr, tid);   // 2051 -> 1029
    __syncthreads();
    dwt16<false>(B16, c3, L2, s3, IN16, c3, d3, nullptr, tid);  // 1029 -> 518
    __syncthreads();
    dwt16<false>(IN16, c3, L3, s3, A16, c3, d4, nullptr, tid);  // 518  -> 262
    __syncthreads();
    dwt16<true>(A16, c3, L4, s3, nullptr, 0, d5, ap, tid);      // 262  -> 134
}

extern "C" void kernel_launch(void* const* d_in, const int* in_sizes, int n_in,
                              void* d_out, int out_size) {
    const float* x = (const float*)d_in[0];
    float* out = (float*)d_out;
    (void)in_sizes; (void)n_in; (void)out_size;
    wavelet5_kernel<<<NROWS, NT>>>(x, out);
}

// round 16
// speedup vs baseline: 1.1006x; 1.0359x over previous
#include <cuda_runtime.h>
#include <cuda_fp16.h>

// 5-level db4 DWT, symmetric extension. fp16 smem cascade, SCALAR fp32 FMA
// (R5 hot loop), 4 outputs/thread from 2 aligned LDS.128. Adds R6's
// store-alignment machinery WITHOUT f32x2: per-level ext offset c chosen
// (mod 8, via templated window OFF) so interior cA stores are one STS.64
// when alignment permits; input stage stores STS.64.

#define NROWS 4096
#define NT    256

#define L0 4096
#define L1 2051
#define L2 1029
#define L3 518
#define L4 262
#define L5 134

#define O_APPROX 0
#define O_D5 (NROWS * L5)
#define O_D4 (O_D5 + NROWS * L5)
#define O_D3 (O_D4 + NROWS * L4)
#define O_D2 (O_D3 + NROWS * L3)
#define O_D1 (O_D2 + NROWS * L2)

// Reversed filters RF[r] = DEC[7-r]; y[j] = sum_r RF[r] * ext[2j+r]
#define RLO0  0.23037781330885523f
#define RLO1  0.7148465705525415f
#define RLO2  0.6308807679295904f
#define RLO3 -0.02798376941698385f
#define RLO4 -0.18703481171888114f
#define RLO5  0.030841381835986965f
#define RLO6  0.032883011666982945f
#define RLO7 -0.010597401784997278f

#define RHI0 -0.010597401784997278f
#define RHI1 -0.032883011666982945f
#define RHI2  0.030841381835986965f
#define RHI3  0.18703481171888114f
#define RHI4 -0.02798376941698385f
#define RHI5 -0.6308807679295904f
#define RHI6  0.7148465705525415f
#define RHI7 -0.23037781330885523f

// Choose window offset / ext base c for level k so the PREVIOUS level's
// interior cA store is maximally aligned. Load alignment needs
// c = 8 + ((2*sk + 2*off) & 7).
__device__ __forceinline__ void pickc(int sk, int sp, int& off, int& c, int& cb,
                                      int& smode) {
    const int v0 = 2 * sk,     ca  = 8 + (v0 & 7), a0 = (ca + 6 - sp) & 3;
    const int v1 = 2 * sk + 2, cbv = 8 + (v1 & 7), a1 = (cbv + 6 - sp) & 3;
    const int r0 = (a0 == 0) ? 0 : ((a0 == 2) ? 1 : 2);
    const int r1 = (a1 == 0) ? 0 : ((a1 == 2) ? 1 : 2);
    if (r1 < r0) { off = 1; c = cbv; cb = cbv - v1; smode = (a1 == 0) ? 0 : ((a1 == 2) ? 2 : 1); }
    else         { off = 0; c = ca;  cb = ca - v0;  smode = (a0 == 0) ? 0 : ((a0 == 2) ? 2 : 1); }
}

// One level: M outputs. q: fp16 ext buffer, loads 2 aligned uint4 from q+cb;
// window w0 = word OFF of the 8 loaded words. j0 = 4T - sigma.
// cD -> fp32 gmem (STG.128 interior). !LAST: cA -> qn at cst = c_next + 6
// (smode 0: STS.64, 2: 2x STS.32, 1: scalar). LAST: cA -> fp32 gmem cAg.
template<int OFF, bool LAST>
__device__ __forceinline__ void lvl(const __half* __restrict__ q, int cb,
                                    int M, int sigma,
                                    __half* __restrict__ qn, int cst, int smode,
                                    float* __restrict__ cD,
                                    float* __restrict__ cAg, int tid) {
    const uint4* __restrict__ Q4 = reinterpret_cast<const uint4*>(q + cb);
    const int NB = (M + sigma + 3) >> 2;

    for (int T = tid; T < NB; T += NT) {
        const uint4 A = Q4[T];
        const uint4 B = Q4[T + 1];
        const unsigned int W[8] = {A.x, A.y, A.z, A.w, B.x, B.y, B.z, B.w};
        float w[14];
#pragma unroll
        for (int p = 0; p < 7; p++) {
            const unsigned int u = W[p + OFF];
            const __half2 hh = *reinterpret_cast<const __half2*>(&u);
            const float2 t = __half22float2(hh);
            w[2 * p] = t.x;
            w[2 * p + 1] = t.y;
        }

        float lo[4], hi[4];
#pragma unroll
        for (int m = 0; m < 4; m++) {
            float l = RLO0 * w[2 * m];
            l = fmaf(RLO1, w[2 * m + 1], l);
            l = fmaf(RLO2, w[2 * m + 2], l);
            l = fmaf(RLO3, w[2 * m + 3], l);
            l = fmaf(RLO4, w[2 * m + 4], l);
            l = fmaf(RLO5, w[2 * m + 5], l);
            l = fmaf(RLO6, w[2 * m + 6], l);
            l = fmaf(RLO7, w[2 * m + 7], l);
            lo[m] = l;
            float h = RHI0 * w[2 * m];
            h = fmaf(RHI1, w[2 * m + 1], h);
            h = fmaf(RHI2, w[2 * m + 2], h);
            h = fmaf(RHI3, w[2 * m + 3], h);
            h = fmaf(RHI4, w[2 * m + 4], h);
            h = fmaf(RHI5, w[2 * m + 5], h);
            h = fmaf(RHI6, w[2 * m + 6], h);
            h = fmaf(RHI7, w[2 * m + 7], h);
            hi[m] = h;
        }

        const int j0 = 4 * T - sigma;
        const bool intD = (j0 >= 0) && (j0 + 4 <= M);
        if (intD) {
            *reinterpret_cast<float4*>(cD + j0) =
                make_float4(hi[0], hi[1], hi[2], hi[3]);
            if (LAST)
                *reinterpret_cast<float4*>(cAg + j0) =
                    make_float4(lo[0], lo[1], lo[2], lo[3]);
        } else {
#pragma unroll
            for (int m = 0; m < 4; m++) {
                const int j = j0 + m;
                if (j >= 0 && j < M) {
                    cD[j] = hi[m];
                    if (LAST) cAg[j] = lo[m];
                }
            }
        }

        if (!LAST) {
            const bool intA = intD && (j0 > 5) && (j0 + 3 < M - 8);
            if (intA) {
                const __half2 p01 = __floats2half2_rn(lo[0], lo[1]);
                const __half2 p23 = __floats2half2_rn(lo[2], lo[3]);
                if (smode == 0) {
                    uint2 v;
                    v.x = *reinterpret_cast<const unsigned int*>(&p01);
                    v.y = *reinterpret_cast<const unsigned int*>(&p23);
                    *reinterpret_cast<uint2*>(qn + cst + j0) = v;
                } else if (smode == 2) {
                    *reinterpret_cast<__half2*>(qn + cst + j0)     = p01;
                    *reinterpret_cast<__half2*>(qn + cst + j0 + 2) = p23;
                } else {
                    qn[cst + j0]     = __low2half(p01);
                    qn[cst + j0 + 1] = __high2half(p01);
                    qn[cst + j0 + 2] = __low2half(p23);
                    qn[cst + j0 + 3] = __high2half(p23);
                }
            } else {
#pragma unroll
                for (int m = 0; m < 4; m++) {
                    const int j = j0 + m;
                    if (j < 0 || j >= M) continue;
                    const __half v = __float2half_rn(lo[m]);
                    qn[cst + j] = v;                          // interior
                    if (j <= 5)     qn[cst - 1 - j] = v;      // left mirror
                    if (j >= M - 8) qn[cst + 2 * M - 1 - j] = v; // right mirror
                }
            }
        }
    }
}

__global__ __launch_bounds__(NT)
void wavelet5_kernel(const float* __restrict__ x, float* __restrict__ out) {
    __shared__ __align__(16) __half IN16[4160]; // lvl1 in / lvl3 out / lvl4 in
    __shared__ __align__(16) __half A16[2112];  // lvl1 out / lvl2 in / lvl4 out / lvl5 in
    __shared__ __align__(16) __half B16[1088];  // lvl2 out / lvl3 in

    const int row = blockIdx.x;
    const int tid = threadIdx.x;

    const int s1 = (3 * row) & 3;   // L1 = 2051 ≡ 3 (mod 4)
    const int s2 = row & 3;         // L2 = 1029 ≡ 1
    const int s3 = (2 * row) & 3;   // L3, L4, L5 ≡ 2

    // Level 1: off forced so the input-stage STS.64 is aligned (c1 ≡ 2 mod 4).
    const int off1 = 1 - (s1 & 1);
    const int v1 = 2 * s1 + 2 * off1;
    const int c1 = 8 + (v1 & 7), cb1 = c1 - v1;

    int off2, c2, cb2, sm1; pickc(s2, s1, off2, c2, cb2, sm1);
    int off3, c3, cb3, sm2; pickc(s3, s2, off3, c3, cb3, sm2);
    int off4, c4, cb4, sm3; pickc(s3, s3, off4, c4, cb4, sm3);
    int off5, c5, cb5, sm4; pickc(s3, s3, off5, c5, cb5, sm4);

    const float* __restrict__ xr = x + (size_t)row * L0;

    // Input stage: ext[i] = IN16[c1 + i]; one float4 -> one STS.64 of 4 halfs.
    {
        const float4* __restrict__ x4 = reinterpret_cast<const float4*>(xr);
        __half* __restrict__ base = IN16 + c1 + 6;
#pragma unroll 4
        for (int u = tid; u < L0 / 4; u += NT) {
            const float4 v = x4[u];
            const __half2 p01 = __floats2half2_rn(v.x, v.y);
            const __half2 p23 = __floats2half2_rn(v.z, v.w);
            uint2 w;
            w.x = *reinterpret_cast<const unsigned int*>(&p01);
            w.y = *reinterpret_cast<const unsigned int*>(&p23);
            *reinterpret_cast<uint2*>(base + 4 * u) = w;
        }
        if (tid < 6) {
            IN16[c1 + tid] = __float2half_rn(xr[5 - tid]);           // left ext
        } else if (tid < 14) {
            const int t = tid - 6;
            IN16[c1 + L0 + 6 + t] = __float2half_rn(xr[L0 - 1 - t]); // right ext
        }
    }
    __syncthreads();

    float* __restrict__ d1 = out + O_D1 + (size_t)row * L1;
    float* __restrict__ d2 = out + O_D2 + (size_t)row * L2;
    float* __restrict__ d3 = out + O_D3 + (size_t)row * L3;
    float* __restrict__ d4 = out + O_D4 + (size_t)row * L4;
    float* __restrict__ d5 = out + O_D5 + (size_t)row * L5;
    float* __restrict__ ap = out + O_APPROX + (size_t)row * L5;

    if (off1) lvl<1, false>(IN16, cb1, L1, s1, A16, c2 + 6, sm1, d1, nullptr, tid);
    else      lvl<0, false>(IN16, cb1, L1, s1, A16, c2 + 6, sm1, d1, nullptr, tid);
    __syncthreads();
    if (off2) lvl<1, false>(A16, cb2, L2, s2, B16, c3 + 6, sm2, d2, nullptr, tid);
    else      lvl<0, false>(A16, cb2, L2, s2, B16, c3 + 6, sm2, d2, nullptr, tid);
    __syncthreads();
    if (off3) lvl<1, false>(B16, cb3, L3, s3, IN16, c4 + 6, sm3, d3, nullptr, tid);
    else      lvl<0, false>(B16, cb3, L3, s3, IN16, c4 + 6, sm3, d3, nullptr, tid);
    __syncthreads();
    if (off4) lvl<1, false>(IN16, cb4, L4, s3, A16, c5 + 6, sm4, d4, nullptr, tid);
    else      lvl<0, false>(IN16, cb4, L4, s3, A16, c5 + 6, sm4, d4, nullptr, tid);
    __syncthreads();
    if (off5) lvl<1, true>(A16, cb5, L5, s3, nullptr, 0, 0, d5, ap, tid);
    else      lvl<0, true>(A16, cb5, L5, s3, nullptr, 0, 0, d5, ap, tid);
}

extern "C" void kernel_launch(void* const* d_in, const int* in_sizes, int n_in,
                              void* d_out, int out_size) {
    const float* x = (const float*)d_in[0];
    float* out = (float*)d_out;
    (void)in_sizes; (void)n_in; (void)out_size;
    wavelet5_kernel<<<NROWS, NT>>>(x, out);
}

// round 17
// speedup vs baseline: 1.1322x; 1.0287x over previous
#include <cuda_runtime.h>
#include <cuda_fp16.h>

// 5-level db4 DWT, symmetric extension. fp16 smem cascade, scalar fp32 FMA,
// 4 outputs/thread, 2 aligned conflict-free LDS.128, sigma-aligned STG.128,
// STS.64 cA stores (R16 body). Tail levels warp-scoped: level 4 runs on
// warps 0-2 with a named 96-thread barrier, level 5 on warps 0-1; warps 3-7
// exit after the level-3 barrier.

#define NROWS 4096
#define NT    256

#define L0 4096
#define L1 2051
#define L2 1029
#define L3 518
#define L4 262
#define L5 134

#define O_APPROX 0
#define O_D5 (NROWS * L5)
#define O_D4 (O_D5 + NROWS * L5)
#define O_D3 (O_D4 + NROWS * L4)
#define O_D2 (O_D3 + NROWS * L3)
#define O_D1 (O_D2 + NROWS * L2)

// Reversed filters RF[r] = DEC[7-r]; y[j] = sum_r RF[r] * ext[2j+r]
#define RLO0  0.23037781330885523f
#define RLO1  0.7148465705525415f
#define RLO2  0.6308807679295904f
#define RLO3 -0.02798376941698385f
#define RLO4 -0.18703481171888114f
#define RLO5  0.030841381835986965f
#define RLO6  0.032883011666982945f
#define RLO7 -0.010597401784997278f

#define RHI0 -0.010597401784997278f
#define RHI1 -0.032883011666982945f
#define RHI2  0.030841381835986965f
#define RHI3  0.18703481171888114f
#define RHI4 -0.02798376941698385f
#define RHI5 -0.6308807679295904f
#define RHI6  0.7148465705525415f
#define RHI7 -0.23037781330885523f

// Choose window offset / ext base c for level k so the PREVIOUS level's
// interior cA store is maximally aligned. Load alignment needs
// c = 8 + ((2*sk + 2*off) & 7).
__device__ __forceinline__ void pickc(int sk, int sp, int& off, int& c, int& cb,
                                      int& smode) {
    const int v0 = 2 * sk,     ca  = 8 + (v0 & 7), a0 = (ca + 6 - sp) & 3;
    const int v1 = 2 * sk + 2, cbv = 8 + (v1 & 7), a1 = (cbv + 6 - sp) & 3;
    const int r0 = (a0 == 0) ? 0 : ((a0 == 2) ? 1 : 2);
    const int r1 = (a1 == 0) ? 0 : ((a1 == 2) ? 1 : 2);
    if (r1 < r0) { off = 1; c = cbv; cb = cbv - v1; smode = (a1 == 0) ? 0 : ((a1 == 2) ? 2 : 1); }
    else         { off = 0; c = ca;  cb = ca - v0;  smode = (a0 == 0) ? 0 : ((a0 == 2) ? 2 : 1); }
}

// One level: M outputs. q: fp16 ext buffer, loads 2 aligned uint4 from q+cb;
// window w0 = word OFF of the 8 loaded words. j0 = 4T - sigma.
// cD -> fp32 gmem (STG.128 interior). !LAST: cA -> qn at cst = c_next + 6
// (smode 0: STS.64, 2: 2x STS.32, 1: scalar). LAST: cA -> fp32 gmem cAg.
template<int OFF, bool LAST>
__device__ __forceinline__ void lvl(const __half* __restrict__ q, int cb,
                                    int M, int sigma,
                                    __half* __restrict__ qn, int cst, int smode,
                                    float* __restrict__ cD,
                                    float* __restrict__ cAg, int tid) {
    const uint4* __restrict__ Q4 = reinterpret_cast<const uint4*>(q + cb);
    const int NB = (M + sigma + 3) >> 2;

    for (int T = tid; T < NB; T += NT) {
        const uint4 A = Q4[T];
        const uint4 B = Q4[T + 1];
        const unsigned int W[8] = {A.x, A.y, A.z, A.w, B.x, B.y, B.z, B.w};
        float w[14];
#pragma unroll
        for (int p = 0; p < 7; p++) {
            const unsigned int u = W[p + OFF];
            const __half2 hh = *reinterpret_cast<const __half2*>(&u);
            const float2 t = __half22float2(hh);
            w[2 * p] = t.x;
            w[2 * p + 1] = t.y;
        }

        float lo[4], hi[4];
#pragma unroll
        for (int m = 0; m < 4; m++) {
            float l = RLO0 * w[2 * m];
            l = fmaf(RLO1, w[2 * m + 1], l);
            l = fmaf(RLO2, w[2 * m + 2], l);
            l = fmaf(RLO3, w[2 * m + 3], l);
            l = fmaf(RLO4, w[2 * m + 4], l);
            l = fmaf(RLO5, w[2 * m + 5], l);
            l = fmaf(RLO6, w[2 * m + 6], l);
            l = fmaf(RLO7, w[2 * m + 7], l);
            lo[m] = l;
            float h = RHI0 * w[2 * m];
            h = fmaf(RHI1, w[2 * m + 1], h);
            h = fmaf(RHI2, w[2 * m + 2], h);
            h = fmaf(RHI3, w[2 * m + 3], h);
            h = fmaf(RHI4, w[2 * m + 4], h);
            h = fmaf(RHI5, w[2 * m + 5], h);
            h = fmaf(RHI6, w[2 * m + 6], h);
            h = fmaf(RHI7, w[2 * m + 7], h);
            hi[m] = h;
        }

        const int j0 = 4 * T - sigma;
        const bool intD = (j0 >= 0) && (j0 + 4 <= M);
        if (intD) {
            *reinterpret_cast<float4*>(cD + j0) =
                make_float4(hi[0], hi[1], hi[2], hi[3]);
            if (LAST)
                *reinterpret_cast<float4*>(cAg + j0) =
                    make_float4(lo[0], lo[1], lo[2], lo[3]);
        } else {
#pragma unroll
            for (int m = 0; m < 4; m++) {
                const int j = j0 + m;
                if (j >= 0 && j < M) {
                    cD[j] = hi[m];
                    if (LAST) cAg[j] = lo[m];
                }
            }
        }

        if (!LAST) {
            const bool intA = intD && (j0 > 5) && (j0 + 3 < M - 8);
            if (intA) {
                const __half2 p01 = __floats2half2_rn(lo[0], lo[1]);
                const __half2 p23 = __floats2half2_rn(lo[2], lo[3]);
                if (smode == 0) {
                    uint2 v;
                    v.x = *reinterpret_cast<const unsigned int*>(&p01);
                    v.y = *reinterpret_cast<const unsigned int*>(&p23);
                    *reinterpret_cast<uint2*>(qn + cst + j0) = v;
                } else if (smode == 2) {
                    *reinterpret_cast<__half2*>(qn + cst + j0)     = p01;
                    *reinterpret_cast<__half2*>(qn + cst + j0 + 2) = p23;
                } else {
                    qn[cst + j0]     = __low2half(p01);
                    qn[cst + j0 + 1] = __high2half(p01);
                    qn[cst + j0 + 2] = __low2half(p23);
                    qn[cst + j0 + 3] = __high2half(p23);
                }
            } else {
#pragma unroll
                for (int m = 0; m < 4; m++) {
                    const int j = j0 + m;
                    if (j < 0 || j >= M) continue;
                    const __half v = __float2half_rn(lo[m]);
                    qn[cst + j] = v;                          // interior
                    if (j <= 5)     qn[cst - 1 - j] = v;      // left mirror
                    if (j >= M - 8) qn[cst + 2 * M - 1 - j] = v; // right mirror
                }
            }
        }
    }
}

__global__ __launch_bounds__(NT)
void wavelet5_kernel(const float* __restrict__ x, float* __restrict__ out) {
    __shared__ __align__(16) __half IN16[4160]; // lvl1 in / lvl3 out / lvl4 in
    __shared__ __align__(16) __half A16[2112];  // lvl1 out / lvl2 in / lvl4 out / lvl5 in
    __shared__ __align__(16) __half B16[1088];  // lvl2 out / lvl3 in

    const int row = blockIdx.x;
    const int tid = threadIdx.x;

    const int s1 = (3 * row) & 3;   // L1 = 2051 ≡ 3 (mod 4)
    const int s2 = row & 3;         // L2 = 1029 ≡ 1
    const int s3 = (2 * row) & 3;   // L3, L4, L5 ≡ 2

    // Level 1: off forced so the input-stage STS.64 is aligned (c1 ≡ 2 mod 4).
    const int off1 = 1 - (s1 & 1);
    const int v1 = 2 * s1 + 2 * off1;
    const int c1 = 8 + (v1 & 7), cb1 = c1 - v1;

    int off2, c2, cb2, sm1; pickc(s2, s1, off2, c2, cb2, sm1);
    int off3, c3, cb3, sm2; pickc(s3, s2, off3, c3, cb3, sm2);
    int off4, c4, cb4, sm3; pickc(s3, s3, off4, c4, cb4, sm3);
    int off5, c5, cb5, sm4; pickc(s3, s3, off5, c5, cb5, sm4);

    const float* __restrict__ xr = x + (size_t)row * L0;

    // Input stage: ext[i] = IN16[c1 + i]; one float4 -> one STS.64 of 4 halfs.
    {
        const float4* __restrict__ x4 = reinterpret_cast<const float4*>(xr);
        __half* __restrict__ base = IN16 + c1 + 6;
#pragma unroll 4
        for (int u = tid; u < L0 / 4; u += NT) {
            const float4 v = x4[u];
            const __half2 p01 = __floats2half2_rn(v.x, v.y);
            const __half2 p23 = __floats2half2_rn(v.z, v.w);
            uint2 w;
            w.x = *reinterpret_cast<const unsigned int*>(&p01);
            w.y = *reinterpret_cast<const unsigned int*>(&p23);
            *reinterpret_cast<uint2*>(base + 4 * u) = w;
        }
        if (tid < 6) {
            IN16[c1 + tid] = __float2half_rn(xr[5 - tid]);           // left ext
        } else if (tid < 14) {
            const int t = tid - 6;
            IN16[c1 + L0 + 6 + t] = __float2half_rn(xr[L0 - 1 - t]); // right ext
        }
    }
    __syncthreads();

    float* __restrict__ d1 = out + O_D1 + (size_t)row * L1;
    float* __restrict__ d2 = out + O_D2 + (size_t)row * L2;
    float* __restrict__ d3 = out + O_D3 + (size_t)row * L3;
    float* __restrict__ d4 = out + O_D4 + (size_t)row * L4;
    float* __restrict__ d5 = out + O_D5 + (size_t)row * L5;
    float* __restrict__ ap = out + O_APPROX + (size_t)row * L5;

    if (off1) lvl<1, false>(IN16, cb1, L1, s1, A16, c2 + 6, sm1, d1, nullptr, tid);
    else      lvl<0, false>(IN16, cb1, L1, s1, A16, c2 + 6, sm1, d1, nullptr, tid);
    __syncthreads();
    if (off2) lvl<1, false>(A16, cb2, L2, s2, B16, c3 + 6, sm2, d2, nullptr, tid);
    else      lvl<0, false>(A16, cb2, L2, s2, B16, c3 + 6, sm2, d2, nullptr, tid);
    __syncthreads();
    if (off3) lvl<1, false>(B16, cb3, L3, s3, IN16, c4 + 6, sm3, d3, nullptr, tid);
    else      lvl<0, false>(B16, cb3, L3, s3, IN16, c4 + 6, sm3, d3, nullptr, tid);
    __syncthreads();

    // Tail levels warp-scoped: level 4 (NB=66) on warps 0-2, level 5 (NB=34)
    // on warps 0-1. Warps 3-7 exit now. Named barrier drains level-4 STS for
    // its participants; no later full-CTA barrier exists (no deadlock).
    if (tid < 96) {
        if (off4) lvl<1, false>(IN16, cb4, L4, s3, A16, c5 + 6, sm4, d4, nullptr, tid);
        else      lvl<0, false>(IN16, cb4, L4, s3, A16, c5 + 6, sm4, d4, nullptr, tid);
        asm volatile("bar.sync 1, 96;" ::: "memory");
        if (tid < 64) {
            if (off5) lvl<1, true>(A16, cb5, L5, s3, nullptr, 0, 0, d5, ap, tid);
            else      lvl<0, true>(A16, cb5, L5, s3, nullptr, 0, 0, d5, ap, tid);
        }
    }
}

extern "C" void kernel_launch(void* const* d_in, const int* in_sizes, int n_in,
                              void* d_out, int out_size) {
    const float* x = (const float*)d_in[0];
    float* out = (float*)d_out;
    (void)in_sizes; (void)n_in; (void)out_size;
    wavelet5_kernel<<<NROWS, NT>>>(x, out);
}